// round 9
// baseline (speedup 1.0000x reference)
#include <cuda_runtime.h>
#include <cuda_bf16.h>

// WaveletLinear: y[b,o] = sum_i w[o,i] * (1 - s^2) * exp(-0.5 s^2),
//   s = (x[b,i] - t[o,i]) / (A_MIN + softplus(scale_raw[o,i]) + EPS)
// B=512, O=1024, I=512.
//
// Math:  c^2 = 1/(2 ln2),  u = (c*s)^2 (>=0, clamped to 60)
//   exp(-0.5 s^2) = 2^(-u)   via ex2.approx.f16x2 (1 MUFU slot / 2 elems)
//   w*(1 - s^2)   = fma(w2n, u, w),  w2n = -2ln2*w
// Post-exp stays in f16: p converted to f16x2, product+accumulate via
// fma.rn.f16x2 into f16x2 accumulators (2 per row), folded to f32 at end.
// No cvt.f32.f16 in the hot loop -> MUFU halved without issue-slot blowup.

#define I_DIM 512
#define RB 8   // batch rows per warp

typedef unsigned long long u64;
typedef unsigned int u32;

__device__ float g_ivc[1024 * 512];
__device__ float g_tin[1024 * 512];
__device__ float g_w2n[1024 * 512];

__device__ __forceinline__ u64 fma2(u64 a, u64 b, u64 c) {
    u64 d; asm("fma.rn.f32x2 %0, %1, %2, %3;" : "=l"(d) : "l"(a), "l"(b), "l"(c)); return d;
}
__device__ __forceinline__ u64 mul2(u64 a, u64 b) {
    u64 d; asm("mul.rn.f32x2 %0, %1, %2;" : "=l"(d) : "l"(a), "l"(b)); return d;
}
__device__ __forceinline__ u64 pack2(float lo, float hi) {
    u64 d; asm("mov.b64 %0, {%1, %2};" : "=l"(d) : "f"(lo), "f"(hi)); return d;
}
__device__ __forceinline__ float lo32(u64 v) { return __uint_as_float((unsigned)v); }
__device__ __forceinline__ float hi32(u64 v) { return __uint_as_float((unsigned)(v >> 32)); }

// {lo: 2^-ul, hi: 2^-uh} as f16x2.  ul,uh >= 0 (sign-xor negation valid).
__device__ __forceinline__ u32 exp2n_f16x2(float ul, float uh) {
    u32 r;
    asm("{\n\t"
        ".reg .b32 h;\n\t"
        "cvt.rn.f16x2.f32 h, %2, %1;\n\t"   // hi <- uh, lo <- ul
        "xor.b32 h, h, 0x80008000;\n\t"     // negate both halves
        "ex2.approx.f16x2 %0, h;\n\t"
        "}" : "=r"(r) : "f"(ul), "f"(uh));
    return r;
}
__device__ __forceinline__ u32 cvt_f16x2(float lo, float hi) {
    u32 r; asm("cvt.rn.f16x2.f32 %0, %2, %1;" : "=r"(r) : "f"(lo), "f"(hi)); return r;
}
__device__ __forceinline__ u32 hfma2(u32 a, u32 b, u32 c) {
    u32 d; asm("fma.rn.f16x2 %0, %1, %2, %3;" : "=r"(d) : "r"(a), "r"(b), "r"(c)); return d;
}
__device__ __forceinline__ float h2sum(u32 h) {   // f16x2 -> f32 lo+hi
    float a, b;
    asm("{\n\t"
        ".reg .b16 x, y;\n\t"
        "mov.b32 {x, y}, %2;\n\t"
        "cvt.f32.f16 %0, x;\n\t"
        "cvt.f32.f16 %1, y;\n\t"
        "}" : "=f"(a), "=f"(b) : "r"(h));
    return a + b;
}

#define C_FOLD   0.84932180028801905f    // sqrt(1/(2 ln2))
#define TWO_LN2  1.38629436111989062f    // 2 ln2
#define NINV2LN2 (-0.72134752044448170f) // -1/(2 ln2)
#define U_CLAMP  60.0f                   // 2^-60 -> 0 in f16; keeps p finite in f16

__global__ void prep_kernel(const float* __restrict__ t,
                            const float* __restrict__ sraw,
                            const float* __restrict__ w,
                            int n)
{
    int idx = blockIdx.x * blockDim.x + threadIdx.x;
    if (idx < n) {
        float z  = sraw[idx];
        float sp = log1pf(__expf(z));
        float sc = 0.001f + sp + 1e-8f;
        float iv = 1.0f / sc;
        g_ivc[idx] = C_FOLD * iv;
        g_tin[idx] = -C_FOLD * t[idx] * iv;
        g_w2n[idx] = -TWO_LN2 * w[idx];
    }
}

__global__ __launch_bounds__(256, 4)
void wavelet_kernel(const float* __restrict__ x,
                    float* __restrict__ out,
                    int O)
{
    const int warp = (blockIdx.x * 256 + threadIdx.x) >> 5;
    const int lane = threadIdx.x & 31;
    const int o  = warp >> 6;       // 8 warps (one block) share o
    const int bt = warp & 63;
    const int b0 = bt * RB;

    const ulonglong2* __restrict__ ivp = (const ulonglong2*)(g_ivc + (size_t)o * I_DIM);
    const ulonglong2* __restrict__ tnp = (const ulonglong2*)(g_tin + (size_t)o * I_DIM);
    const ulonglong2* __restrict__ w2p = (const ulonglong2*)(g_w2n + (size_t)o * I_DIM);
    const ulonglong2* __restrict__ xp  = (const ulonglong2*)(x     + (size_t)b0 * I_DIM);

    const u64 KINV = pack2(NINV2LN2, NINV2LN2);

    // two f16x2 accumulators per row (pair0 / pair1) to limit f16 rounding
    u32 accA[RB], accB[RB];
#pragma unroll
    for (int b = 0; b < RB; b++) { accA[b] = 0u; accB[b] = 0u; }

#pragma unroll
    for (int step = 0; step < I_DIM / 128; step++) {
        const int i4 = step * 32 + lane;   // 128-bit index: 128 i per step
        const ulonglong2 iv = ivp[i4];
        const ulonglong2 tn = tnp[i4];
        const ulonglong2 w2 = w2p[i4];
        const u64 wvx = mul2(w2.x, KINV);  // reconstruct w once per step
        const u64 wvy = mul2(w2.y, KINV);

#pragma unroll
        for (int b = 0; b < RB; b++) {
            const ulonglong2 xv = xp[i4 + b * (I_DIM / 4)];

            // pair 0 -> accA
            {
                u64 s  = fma2(xv.x, iv.x, tn.x);
                u64 u  = mul2(s, s);
                float ul = fminf(lo32(u), U_CLAMP);
                float uh = fminf(hi32(u), U_CLAMP);
                u32 eh = exp2n_f16x2(ul, uh);
                u64 pp = fma2(w2.x, pack2(ul, uh), wvx);
                u32 ph = cvt_f16x2(lo32(pp), hi32(pp));
                accA[b] = hfma2(ph, eh, accA[b]);
            }
            // pair 1 -> accB
            {
                u64 s  = fma2(xv.y, iv.y, tn.y);
                u64 u  = mul2(s, s);
                float ul = fminf(lo32(u), U_CLAMP);
                float uh = fminf(hi32(u), U_CLAMP);
                u32 eh = exp2n_f16x2(ul, uh);
                u64 pp = fma2(w2.y, pack2(ul, uh), wvy);
                u32 ph = cvt_f16x2(lo32(pp), hi32(pp));
                accB[b] = hfma2(ph, eh, accB[b]);
            }
        }
    }

    // fold f16x2 accs to f32, then warp reduction over i-lanes
#pragma unroll
    for (int b = 0; b < RB; b++) {
        float a = h2sum(accA[b]) + h2sum(accB[b]);
#pragma unroll
        for (int off = 16; off > 0; off >>= 1)
            a += __shfl_xor_sync(0xFFFFFFFFu, a, off);
        if (lane == 0)
            out[(size_t)(b0 + b) * O + o] = a;
    }
}

extern "C" void kernel_launch(void* const* d_in, const int* in_sizes, int n_in,
                              void* d_out, int out_size)
{
    const float* x    = (const float*)d_in[0];  // (B, I)
    const float* t    = (const float*)d_in[1];  // (O, I)
    const float* sraw = (const float*)d_in[2];  // (O, I)
    const float* w    = (const float*)d_in[3];  // (O, I)
    float* out = (float*)d_out;                 // (B, O)

    const int OI = in_sizes[1];          // O * I
    const int BI = in_sizes[0];          // B * I
    const int O  = OI / I_DIM;           // 1024
    const int B  = BI / I_DIM;           // 512
    const int nbt = B / RB;              // 64

    prep_kernel<<<(OI + 255) / 256, 256>>>(t, sraw, w, OI);

    const int total_warps = O * nbt;
    wavelet_kernel<<<total_warps / 8, 256>>>(x, out, O);
}

// round 10
// speedup vs baseline: 1.0731x; 1.0731x over previous
#include <cuda_runtime.h>
#include <cuda_bf16.h>

// WaveletLinear: y[b,o] = sum_i w[o,i] * (1 - s^2) * exp(-0.5 s^2),
//   s = (x[b,i] - t[o,i]) / (A_MIN + softplus(scale_raw[o,i]) + EPS)
// B=512, O=1024, I=512.
//
// Math: u = (c*s)^2 >= 0, c^2 = 1/(2 ln2):
//   exp(-0.5 s^2) = 2^(-u) via ex2.approx.f16x2 (1 MUFU slot per 2 elems;
//                   negation = sign-bit xor; no clamps: u<=~1500 is f16-safe,
//                   e underflows to 0 and p = w(1-s^2) stays < 400)
//   w*(1-s^2) = fma(w2n, u, w) in f32x2, w2n = -2ln2*w
// Accumulate p*e with fma.rn.f16x2; fold to f32 mid-loop + at end so each
// f16 chain is <= 4 adds (validated error model ~5.5e-4).
//
// Layout: warp owns RO=2 outputs x RB=8 batch rows -> each x-row load feeds
// 2 outputs, halving the L1-wavefront floor (53us -> 34us).

#define I_DIM 512
#define RB 8
#define RO 2

typedef unsigned long long u64;
typedef unsigned int u32;

__device__ float g_ivc[1024 * 512];
__device__ float g_tin[1024 * 512];
__device__ float g_w2n[1024 * 512];

__device__ __forceinline__ u64 fma2(u64 a, u64 b, u64 c) {
    u64 d; asm("fma.rn.f32x2 %0, %1, %2, %3;" : "=l"(d) : "l"(a), "l"(b), "l"(c)); return d;
}
__device__ __forceinline__ u64 mul2(u64 a, u64 b) {
    u64 d; asm("mul.rn.f32x2 %0, %1, %2;" : "=l"(d) : "l"(a), "l"(b)); return d;
}
__device__ __forceinline__ u64 pack2(float lo, float hi) {
    u64 d; asm("mov.b64 %0, {%1, %2};" : "=l"(d) : "f"(lo), "f"(hi)); return d;
}

// packed f32x2 u (>=0) -> f16x2 {2^-u.lo, 2^-u.hi}
__device__ __forceinline__ u32 exp2n_h2(u64 u) {
    u32 r;
    asm("{\n\t"
        ".reg .b32 lo, hi, h;\n\t"
        "mov.b64 {lo, hi}, %1;\n\t"
        "cvt.rn.f16x2.f32 h, hi, lo;\n\t"   // lower<-lo, upper<-hi
        "xor.b32 h, h, 0x80008000;\n\t"     // negate both halves (u>=0)
        "ex2.approx.f16x2 %0, h;\n\t"
        "}" : "=r"(r) : "l"(u));
    return r;
}
// packed f32x2 -> f16x2
__device__ __forceinline__ u32 cvt_h2(u64 p) {
    u32 r;
    asm("{\n\t"
        ".reg .b32 lo, hi;\n\t"
        "mov.b64 {lo, hi}, %1;\n\t"
        "cvt.rn.f16x2.f32 %0, hi, lo;\n\t"
        "}" : "=r"(r) : "l"(p));
    return r;
}
__device__ __forceinline__ u32 hfma2(u32 a, u32 b, u32 c) {
    u32 d; asm("fma.rn.f16x2 %0, %1, %2, %3;" : "=r"(d) : "r"(a), "r"(b), "r"(c)); return d;
}
__device__ __forceinline__ float h2sum(u32 h) {   // f16x2 -> f32 lo+hi
    float a, b;
    asm("{\n\t"
        ".reg .b16 x, y;\n\t"
        "mov.b32 {x, y}, %2;\n\t"
        "cvt.f32.f16 %0, x;\n\t"
        "cvt.f32.f16 %1, y;\n\t"
        "}" : "=f"(a), "=f"(b) : "r"(h));
    return a + b;
}

#define C_FOLD   0.84932180028801905f    // sqrt(1/(2 ln2))
#define TWO_LN2  1.38629436111989062f    // 2 ln2
#define NINV2LN2 (-0.72134752044448170f) // -1/(2 ln2)

__global__ void prep_kernel(const float* __restrict__ t,
                            const float* __restrict__ sraw,
                            const float* __restrict__ w,
                            int n)
{
    int idx = blockIdx.x * blockDim.x + threadIdx.x;
    if (idx < n) {
        float z  = sraw[idx];
        float sp = log1pf(__expf(z));
        float sc = 0.001f + sp + 1e-8f;
        float iv = 1.0f / sc;
        g_ivc[idx] = C_FOLD * iv;
        g_tin[idx] = -C_FOLD * t[idx] * iv;
        g_w2n[idx] = -TWO_LN2 * w[idx];
    }
}

__global__ __launch_bounds__(256, 3)
void wavelet_kernel(const float* __restrict__ x,
                    float* __restrict__ out,
                    int O)
{
    const int wid  = threadIdx.x >> 5;
    const int lane = threadIdx.x & 31;
    const int og = blockIdx.x & 63;    // O/16 groups, varies fastest
    const int bt = blockIdx.x >> 6;    // co-resident blocks share x tile
    const int o0 = og * 16 + wid * 2;  // this warp's two outputs: o0, o0+1
    const int b0 = bt * RB;

    // ulonglong2 units: 128 per row of 512 floats
    const ulonglong2* __restrict__ ivp = ((const ulonglong2*)g_ivc) + (size_t)o0 * 128;
    const ulonglong2* __restrict__ tnp = ((const ulonglong2*)g_tin) + (size_t)o0 * 128;
    const ulonglong2* __restrict__ w2p = ((const ulonglong2*)g_w2n) + (size_t)o0 * 128;
    const ulonglong2* __restrict__ xp  = ((const ulonglong2*)x)     + (size_t)b0 * 128;

    const u64 KINV = pack2(NINV2LN2, NINV2LN2);

    float facc[RO][RB];   // f32 master accumulators
    u32   hacc[RO][RB];   // f16x2 short-chain accumulators
#pragma unroll
    for (int q = 0; q < RO; q++)
#pragma unroll
        for (int b = 0; b < RB; b++) { facc[q][b] = 0.0f; hacc[q][b] = 0u; }

#pragma unroll
    for (int step = 0; step < 4; step++) {
        const int i4 = step * 32 + lane;

        // load x tile for this step: 8 rows, reused by both outputs
        ulonglong2 xv[RB];
#pragma unroll
        for (int b = 0; b < RB; b++) xv[b] = xp[i4 + b * 128];

#pragma unroll
        for (int q = 0; q < RO; q++) {
            const ulonglong2 iv = ivp[q * 128 + i4];
            const ulonglong2 tn = tnp[q * 128 + i4];
            const ulonglong2 w2 = w2p[q * 128 + i4];
            const u64 wvx = mul2(w2.x, KINV);  // reconstruct w once per step
            const u64 wvy = mul2(w2.y, KINV);

#pragma unroll
            for (int b = 0; b < RB; b++) {
                // pair 0
                {
                    u64 s  = fma2(xv[b].x, iv.x, tn.x);
                    u64 u  = mul2(s, s);
                    u32 eh = exp2n_h2(u);
                    u64 pp = fma2(w2.x, u, wvx);
                    hacc[q][b] = hfma2(cvt_h2(pp), eh, hacc[q][b]);
                }
                // pair 1
                {
                    u64 s  = fma2(xv[b].y, iv.y, tn.y);
                    u64 u  = mul2(s, s);
                    u32 eh = exp2n_h2(u);
                    u64 pp = fma2(w2.y, u, wvy);
                    hacc[q][b] = hfma2(cvt_h2(pp), eh, hacc[q][b]);
                }
            }
        }

        // mid-loop fold: keep f16 chains <= 4 adds
        if (step == 1) {
#pragma unroll
            for (int q = 0; q < RO; q++)
#pragma unroll
                for (int b = 0; b < RB; b++) {
                    facc[q][b] += h2sum(hacc[q][b]);
                    hacc[q][b] = 0u;
                }
        }
    }

    // final fold + warp reduction over i-lanes
#pragma unroll
    for (int q = 0; q < RO; q++) {
#pragma unroll
        for (int b = 0; b < RB; b++) {
            float a = facc[q][b] + h2sum(hacc[q][b]);
#pragma unroll
            for (int off = 16; off > 0; off >>= 1)
                a += __shfl_xor_sync(0xFFFFFFFFu, a, off);
            if (lane == 0)
                out[(size_t)(b0 + b) * O + (o0 + q)] = a;
        }
    }
}

extern "C" void kernel_launch(void* const* d_in, const int* in_sizes, int n_in,
                              void* d_out, int out_size)
{
    const float* x    = (const float*)d_in[0];  // (B, I)
    const float* t    = (const float*)d_in[1];  // (O, I)
    const float* sraw = (const float*)d_in[2];  // (O, I)
    const float* w    = (const float*)d_in[3];  // (O, I)
    float* out = (float*)d_out;                 // (B, O)

    const int OI = in_sizes[1];          // O * I
    const int BI = in_sizes[0];          // B * I
    const int O  = OI / I_DIM;           // 1024
    const int B  = BI / I_DIM;           // 512

    prep_kernel<<<(OI + 255) / 256, 256>>>(t, sraw, w, OI);

    // blocks = (O/16) o-groups * (B/8) batch tiles = 64*64 = 4096
    wavelet_kernel<<<(O / 16) * (B / RB), 256>>>(x, out, O);
}

// round 12
// speedup vs baseline: 1.0846x; 1.0107x over previous
#include <cuda_runtime.h>
#include <cuda_bf16.h>

// WaveletLinear: y[b,o] = sum_i w[o,i] * (1 - s^2) * exp(-0.5 s^2),
//   s = (x[b,i] - t[o,i]) / (A_MIN + softplus(scale_raw[o,i]) + EPS)
// B=512, O=1024, I=512.
//
// Math:  c^2 = 1/(2 ln2),  u = (c*s)^2 >= 0
//   exp(-0.5 s^2) = 2^(-u);  w*(1-s^2) = fma(w2n, u, w), w2n = -2ln2*w
//
// MUFU floor breaker: offload 1/4 of exps to the FMA pipe via bit-trick exp2.
// FIXED range reduction (r11 bug: u-t at |.|~1.25e7 rounds away the fraction):
//   t = u + M2            (M2 = 1.5*2^23; n = round(u) in t's low mantissa)
//   n = t - M2            (EXACT by Sterbenz)
//   f = u - n             (exact small subtraction, in [-0.5, 0.5])
//   P = deg-4 Taylor of 2^-f;  e_bits = P_bits - (t_bits << 23)
//   (bias*2^23 mod 2^32 = 0, so t_bits works directly in the IMAD)

#define I_DIM 512
#define RB 8   // batch rows per warp

typedef unsigned long long u64;

__device__ float g_ivc[1024 * 512];
__device__ float g_tin[1024 * 512];
__device__ float g_w2n[1024 * 512];

__device__ __forceinline__ u64 fma2(u64 a, u64 b, u64 c) {
    u64 d; asm("fma.rn.f32x2 %0, %1, %2, %3;" : "=l"(d) : "l"(a), "l"(b), "l"(c)); return d;
}
__device__ __forceinline__ u64 mul2(u64 a, u64 b) {
    u64 d; asm("mul.rn.f32x2 %0, %1, %2;" : "=l"(d) : "l"(a), "l"(b)); return d;
}
__device__ __forceinline__ u64 add2(u64 a, u64 b) {
    u64 d; asm("add.rn.f32x2 %0, %1, %2;" : "=l"(d) : "l"(a), "l"(b)); return d;
}
__device__ __forceinline__ float ex2neg(float a) {
    float r;
    asm("{ .reg .f32 t; neg.f32 t, %1; ex2.approx.ftz.f32 %0, t; }" : "=f"(r) : "f"(a));
    return r;
}
__device__ __forceinline__ u64 pack2(float lo, float hi) {
    u64 d; asm("mov.b64 %0, {%1, %2};" : "=l"(d) : "f"(lo), "f"(hi)); return d;
}
__device__ __forceinline__ float lo32(u64 v) { return __uint_as_float((unsigned)v); }
__device__ __forceinline__ float hi32(u64 v) { return __uint_as_float((unsigned)(v >> 32)); }

#define C_FOLD   0.84932180028801905f    // sqrt(1/(2 ln2))
#define TWO_LN2  1.38629436111989062f    // 2 ln2
#define NINV2LN2 (-0.72134752044448170f) // -1/(2 ln2)
#define M2CONST  12582912.0f             // 1.5 * 2^23

// Taylor of 2^(-f), f in [-0.5, 0.5]
#define PC1 (-0.69314718056f)
#define PC2 ( 0.24022650696f)
#define PC3 (-0.05550410866f)
#define PC4 ( 0.00961812911f)

__global__ void prep_kernel(const float* __restrict__ t,
                            const float* __restrict__ sraw,
                            const float* __restrict__ w,
                            int n)
{
    int idx = blockIdx.x * blockDim.x + threadIdx.x;
    if (idx < n) {
        float z  = sraw[idx];
        float sp = log1pf(__expf(z));
        float sc = 0.001f + sp + 1e-8f;
        float iv = 1.0f / sc;
        g_ivc[idx] = C_FOLD * iv;
        g_tin[idx] = -C_FOLD * t[idx] * iv;
        g_w2n[idx] = -TWO_LN2 * w[idx];
    }
}

__global__ __launch_bounds__(256, 3)
void wavelet_kernel(const float* __restrict__ x,
                    float* __restrict__ out,
                    int O)
{
    const int warp = (blockIdx.x * 256 + threadIdx.x) >> 5;
    const int lane = threadIdx.x & 31;
    const int o  = warp >> 6;       // 8 warps (one block) share o
    const int bt = warp & 63;
    const int b0 = bt * RB;

    const ulonglong2* __restrict__ ivp = (const ulonglong2*)(g_ivc + (size_t)o * I_DIM);
    const ulonglong2* __restrict__ tnp = (const ulonglong2*)(g_tin + (size_t)o * I_DIM);
    const ulonglong2* __restrict__ w2p = (const ulonglong2*)(g_w2n + (size_t)o * I_DIM);
    const ulonglong2* __restrict__ xp  = (const ulonglong2*)(x     + (size_t)b0 * I_DIM);

    const u64 KINV = pack2(NINV2LN2, NINV2LN2);
    const u64 M2P  = pack2(M2CONST, M2CONST);
    const u64 M2N  = pack2(-M2CONST, -M2CONST);
    const u64 N1P  = pack2(-1.0f, -1.0f);
    const u64 C1P  = pack2(PC1, PC1);
    const u64 C2P  = pack2(PC2, PC2);
    const u64 C3P  = pack2(PC3, PC3);
    const u64 C4P  = pack2(PC4, PC4);
    const u64 ONEP = pack2(1.0f, 1.0f);

    u64 acc[RB];
#pragma unroll
    for (int b = 0; b < RB; b++) acc[b] = 0ull;

#pragma unroll
    for (int step = 0; step < I_DIM / 128; step++) {
        const int i4 = step * 32 + lane;   // 128-bit index: 128 i per step
        const ulonglong2 iv = ivp[i4];
        const ulonglong2 tn = tnp[i4];
        const ulonglong2 w2 = w2p[i4];
        const u64 wvx = mul2(w2.x, KINV);  // reconstruct w once per step
        const u64 wvy = mul2(w2.y, KINV);
        const bool poly = (step == 0) || (step == 2);   // 1/4 of all pairs

#pragma unroll
        for (int b = 0; b < RB; b++) {
            const ulonglong2 xv = xp[i4 + b * (I_DIM / 4)];

            // pair 0: MUFU f32 path (always)
            {
                u64 s  = fma2(xv.x, iv.x, tn.x);
                u64 u  = mul2(s, s);
                float e0 = ex2neg(lo32(u));
                float e1 = ex2neg(hi32(u));
                u64 ep = pack2(e0, e1);
                u64 pp = fma2(w2.x, u, wvx);
                acc[b] = fma2(pp, ep, acc[b]);
            }
            // pair 1: poly-exp on FMA pipe (steps 0,2), MUFU otherwise
            {
                u64 s  = fma2(xv.y, iv.y, tn.y);
                u64 u  = mul2(s, s);
                u64 pp = fma2(w2.y, u, wvy);
                u64 ep;
                if (poly) {
                    // clamp u to [0,120] for exponent-field safety
                    float ul = fminf(lo32(u), 120.0f);
                    float uh = fminf(hi32(u), 120.0f);
                    u64 uc = pack2(ul, uh);
                    u64 t  = add2(uc, M2P);      // M2 + n (n = round(u))
                    u64 nf = add2(t, M2N);       // n as float (exact, Sterbenz)
                    u64 f  = fma2(nf, N1P, uc);  // f = u - n, in [-0.5, 0.5]
                    u64 P  = fma2(C4P, f, C3P);  // deg-4 Taylor of 2^-f
                    P = fma2(P, f, C2P);
                    P = fma2(P, f, C1P);
                    P = fma2(P, f, ONEP);
                    // e_bits = P_bits - (t_bits << 23); bias term wraps to 0
                    int tb0 = (int)(unsigned)t;
                    int tb1 = (int)(unsigned)(t >> 32);
                    int e0 = __float_as_int(lo32(P)) + tb0 * (-8388608);
                    int e1 = __float_as_int(hi32(P)) + tb1 * (-8388608);
                    ep = pack2(__int_as_float(e0), __int_as_float(e1));
                } else {
                    float e0 = ex2neg(lo32(u));
                    float e1 = ex2neg(hi32(u));
                    ep = pack2(e0, e1);
                }
                acc[b] = fma2(pp, ep, acc[b]);
            }
        }
    }

    // fold packed halves, then warp reduction over i-lanes
#pragma unroll
    for (int b = 0; b < RB; b++) {
        float a = lo32(acc[b]) + hi32(acc[b]);
#pragma unroll
        for (int off = 16; off > 0; off >>= 1)
            a += __shfl_xor_sync(0xFFFFFFFFu, a, off);
        if (lane == 0)
            out[(size_t)(b0 + b) * O + o] = a;
    }
}

extern "C" void kernel_launch(void* const* d_in, const int* in_sizes, int n_in,
                              void* d_out, int out_size)
{
    const float* x    = (const float*)d_in[0];  // (B, I)
    const float* t    = (const float*)d_in[1];  // (O, I)
    const float* sraw = (const float*)d_in[2];  // (O, I)
    const float* w    = (const float*)d_in[3];  // (O, I)
    float* out = (float*)d_out;                 // (B, O)

    const int OI = in_sizes[1];          // O * I
    const int BI = in_sizes[0];          // B * I
    const int O  = OI / I_DIM;           // 1024
    const int B  = BI / I_DIM;           // 512
    const int nbt = B / RB;              // 64

    prep_kernel<<<(OI + 255) / 256, 256>>>(t, sraw, w, OI);

    const int total_warps = O * nbt;
    wavelet_kernel<<<total_warps / 8, 256>>>(x, out, O);
}

// round 13
// speedup vs baseline: 1.1364x; 1.0478x over previous
#include <cuda_runtime.h>
#include <cuda_bf16.h>

// WaveletLinear: y[b,o] = sum_i w[o,i] * (1 - s^2) * exp(-0.5 s^2),
//   s = (x[b,i] - t[o,i]) / (A_MIN + softplus(scale_raw[o,i]) + EPS)
// B=512, O=1024, I=512.
//
// Cost model (RF-banking corrected): fma2 with 3 distinct 64b operands costs
// 3 cyc/SMSP. r3 floor = MUFU 16 cyc/pair (113K cyc, measured). r12 (poly on
// 1/4 pairs) = fma-bound 122K cyc (measured 123K). Optimal poly fraction is
// ~1/8: fma 13.6, MUFU 14.0 -> floor 99.4K cyc (~64us).
//
// Poly path (exact range reduction):
//   t = u + M2; n = t - M2 (Sterbenz-exact); f = u - n in [-0.5,0.5]
//   P = deg-4 Taylor of 2^-f; e_bits = P_bits - (t_bits << 23)

#define I_DIM 512
#define RB 8   // batch rows per warp

typedef unsigned long long u64;

__device__ float g_ivc[1024 * 512];
__device__ float g_tin[1024 * 512];
__device__ float g_w2n[1024 * 512];

__device__ __forceinline__ u64 fma2(u64 a, u64 b, u64 c) {
    u64 d; asm("fma.rn.f32x2 %0, %1, %2, %3;" : "=l"(d) : "l"(a), "l"(b), "l"(c)); return d;
}
__device__ __forceinline__ u64 mul2(u64 a, u64 b) {
    u64 d; asm("mul.rn.f32x2 %0, %1, %2;" : "=l"(d) : "l"(a), "l"(b)); return d;
}
__device__ __forceinline__ u64 add2(u64 a, u64 b) {
    u64 d; asm("add.rn.f32x2 %0, %1, %2;" : "=l"(d) : "l"(a), "l"(b)); return d;
}
__device__ __forceinline__ float ex2neg(float a) {
    float r;
    asm("{ .reg .f32 t; neg.f32 t, %1; ex2.approx.ftz.f32 %0, t; }" : "=f"(r) : "f"(a));
    return r;
}
__device__ __forceinline__ u64 pack2(float lo, float hi) {
    u64 d; asm("mov.b64 %0, {%1, %2};" : "=l"(d) : "f"(lo), "f"(hi)); return d;
}
__device__ __forceinline__ float lo32(u64 v) { return __uint_as_float((unsigned)v); }
__device__ __forceinline__ float hi32(u64 v) { return __uint_as_float((unsigned)(v >> 32)); }

#define C_FOLD   0.84932180028801905f    // sqrt(1/(2 ln2))
#define TWO_LN2  1.38629436111989062f    // 2 ln2
#define NINV2LN2 (-0.72134752044448170f) // -1/(2 ln2)
#define M2CONST  12582912.0f             // 1.5 * 2^23

// Taylor of 2^(-f), f in [-0.5, 0.5]
#define PC1 (-0.69314718056f)
#define PC2 ( 0.24022650696f)
#define PC3 (-0.05550410866f)
#define PC4 ( 0.00961812911f)

__global__ void prep_kernel(const float* __restrict__ t,
                            const float* __restrict__ sraw,
                            const float* __restrict__ w,
                            int n)
{
    int idx = blockIdx.x * blockDim.x + threadIdx.x;
    if (idx < n) {
        float z  = sraw[idx];
        float sp = log1pf(__expf(z));
        float sc = 0.001f + sp + 1e-8f;
        float iv = 1.0f / sc;
        g_ivc[idx] = C_FOLD * iv;
        g_tin[idx] = -C_FOLD * t[idx] * iv;
        g_w2n[idx] = -TWO_LN2 * w[idx];
    }
}

__global__ __launch_bounds__(256, 3)
void wavelet_kernel(const float* __restrict__ x,
                    float* __restrict__ out,
                    int O)
{
    const int warp = (blockIdx.x * 256 + threadIdx.x) >> 5;
    const int lane = threadIdx.x & 31;
    const int o  = warp >> 6;       // 8 warps (one block) share o
    const int bt = warp & 63;
    const int b0 = bt * RB;

    const ulonglong2* __restrict__ ivp = (const ulonglong2*)(g_ivc + (size_t)o * I_DIM);
    const ulonglong2* __restrict__ tnp = (const ulonglong2*)(g_tin + (size_t)o * I_DIM);
    const ulonglong2* __restrict__ w2p = (const ulonglong2*)(g_w2n + (size_t)o * I_DIM);
    const ulonglong2* __restrict__ xp  = (const ulonglong2*)(x     + (size_t)b0 * I_DIM);

    const u64 KINV = pack2(NINV2LN2, NINV2LN2);
    const u64 M2P  = pack2(M2CONST, M2CONST);
    const u64 M2N  = pack2(-M2CONST, -M2CONST);
    const u64 N1P  = pack2(-1.0f, -1.0f);
    const u64 C1P  = pack2(PC1, PC1);
    const u64 C2P  = pack2(PC2, PC2);
    const u64 C3P  = pack2(PC3, PC3);
    const u64 C4P  = pack2(PC4, PC4);
    const u64 ONEP = pack2(1.0f, 1.0f);

    u64 acc[RB];
#pragma unroll
    for (int b = 0; b < RB; b++) acc[b] = 0ull;

#pragma unroll
    for (int step = 0; step < I_DIM / 128; step++) {
        const int i4 = step * 32 + lane;   // 128-bit index: 128 i per step
        const ulonglong2 iv = ivp[i4];
        const ulonglong2 tn = tnp[i4];
        const ulonglong2 w2 = w2p[i4];
        const u64 wvx = mul2(w2.x, KINV);  // reconstruct w once per step
        const u64 wvy = mul2(w2.y, KINV);
        const bool poly = (step == 2);     // poly on pair1 of step 2: g = 1/8

#pragma unroll
        for (int b = 0; b < RB; b++) {
            const ulonglong2 xv = xp[i4 + b * (I_DIM / 4)];

            // pair 0: MUFU f32 path (always)
            {
                u64 s  = fma2(xv.x, iv.x, tn.x);
                u64 u  = mul2(s, s);
                float e0 = ex2neg(lo32(u));
                float e1 = ex2neg(hi32(u));
                u64 ep = pack2(e0, e1);
                u64 pp = fma2(w2.x, u, wvx);
                acc[b] = fma2(pp, ep, acc[b]);
            }
            // pair 1: poly-exp on FMA pipe (step 2 only), MUFU otherwise
            {
                u64 s  = fma2(xv.y, iv.y, tn.y);
                u64 u  = mul2(s, s);
                u64 pp = fma2(w2.y, u, wvy);
                u64 ep;
                if (poly) {
                    // clamp u to [0,120] for exponent-field safety
                    float ul = fminf(lo32(u), 120.0f);
                    float uh = fminf(hi32(u), 120.0f);
                    u64 uc = pack2(ul, uh);
                    u64 t  = add2(uc, M2P);      // M2 + n (n = round(u))
                    u64 nf = add2(t, M2N);       // n as float (exact, Sterbenz)
                    u64 f  = fma2(nf, N1P, uc);  // f = u - n, in [-0.5, 0.5]
                    u64 P  = fma2(C4P, f, C3P);  // deg-4 Taylor of 2^-f
                    P = fma2(P, f, C2P);
                    P = fma2(P, f, C1P);
                    P = fma2(P, f, ONEP);
                    // e_bits = P_bits - (t_bits << 23); bias term wraps to 0
                    int tb0 = (int)(unsigned)t;
                    int tb1 = (int)(unsigned)(t >> 32);
                    int e0 = __float_as_int(lo32(P)) + tb0 * (-8388608);
                    int e1 = __float_as_int(hi32(P)) + tb1 * (-8388608);
                    ep = pack2(__int_as_float(e0), __int_as_float(e1));
                } else {
                    float e0 = ex2neg(lo32(u));
                    float e1 = ex2neg(hi32(u));
                    ep = pack2(e0, e1);
                }
                acc[b] = fma2(pp, ep, acc[b]);
            }
        }
    }

    // fold packed halves, then warp reduction over i-lanes
#pragma unroll
    for (int b = 0; b < RB; b++) {
        float a = lo32(acc[b]) + hi32(acc[b]);
#pragma unroll
        for (int off = 16; off > 0; off >>= 1)
            a += __shfl_xor_sync(0xFFFFFFFFu, a, off);
        if (lane == 0)
            out[(size_t)(b0 + b) * O + o] = a;
    }
}

extern "C" void kernel_launch(void* const* d_in, const int* in_sizes, int n_in,
                              void* d_out, int out_size)
{
    const float* x    = (const float*)d_in[0];  // (B, I)
    const float* t    = (const float*)d_in[1];  // (O, I)
    const float* sraw = (const float*)d_in[2];  // (O, I)
    const float* w    = (const float*)d_in[3];  // (O, I)
    float* out = (float*)d_out;                 // (B, O)

    const int OI = in_sizes[1];          // O * I
    const int BI = in_sizes[0];          // B * I
    const int O  = OI / I_DIM;           // 1024
    const int B  = BI / I_DIM;           // 512
    const int nbt = B / RB;              // 64

    prep_kernel<<<(OI + 255) / 256, 256>>>(t, sraw, w, OI);

    const int total_warps = O * nbt;
    wavelet_kernel<<<total_warps / 8, 256>>>(x, out, O);
}

// round 14
// speedup vs baseline: 1.1531x; 1.0147x over previous
#include <cuda_runtime.h>
#include <cuda_bf16.h>

// WaveletLinear: y[b,o] = sum_i w[o,i] * (1 - s^2) * exp(-0.5 s^2),
//   s = (x[b,i] - t[o,i]) / (A_MIN + softplus(scale_raw[o,i]) + EPS)
// B=512, O=1024, I=512.
//
// Model (validated r3/r13): MUFU binds at 16 cyc/pair (113K cyc). Poly-exp
// offload to the FMA pipe only helps if INTERLEAVED at pair granularity --
// r13 clustered poly in one step and the phases serialized (127K cyc).
// Here: poly on pair1 of b=1 and b=5 (g=1/8, spread through the b-loop):
//   MUFU 16*(7/8)=14.0 cyc/pair, fma 11+21/8=13.6 -> floor ~99K cyc (~66us).
//
// Poly path (exact range reduction):
//   t = u + M2; n = t - M2 (Sterbenz-exact); f = u - n in [-0.5,0.5]
//   P = deg-4 Taylor of 2^-f; e_bits = P_bits - (t_bits << 23)

#define I_DIM 512
#define RB 8   // batch rows per warp

typedef unsigned long long u64;

__device__ float g_ivc[1024 * 512];
__device__ float g_tin[1024 * 512];
__device__ float g_w2n[1024 * 512];

__device__ __forceinline__ u64 fma2(u64 a, u64 b, u64 c) {
    u64 d; asm("fma.rn.f32x2 %0, %1, %2, %3;" : "=l"(d) : "l"(a), "l"(b), "l"(c)); return d;
}
__device__ __forceinline__ u64 mul2(u64 a, u64 b) {
    u64 d; asm("mul.rn.f32x2 %0, %1, %2;" : "=l"(d) : "l"(a), "l"(b)); return d;
}
__device__ __forceinline__ u64 add2(u64 a, u64 b) {
    u64 d; asm("add.rn.f32x2 %0, %1, %2;" : "=l"(d) : "l"(a), "l"(b)); return d;
}
__device__ __forceinline__ float ex2neg(float a) {
    float r;
    asm("{ .reg .f32 t; neg.f32 t, %1; ex2.approx.ftz.f32 %0, t; }" : "=f"(r) : "f"(a));
    return r;
}
__device__ __forceinline__ u64 pack2(float lo, float hi) {
    u64 d; asm("mov.b64 %0, {%1, %2};" : "=l"(d) : "f"(lo), "f"(hi)); return d;
}
__device__ __forceinline__ float lo32(u64 v) { return __uint_as_float((unsigned)v); }
__device__ __forceinline__ float hi32(u64 v) { return __uint_as_float((unsigned)(v >> 32)); }

#define C_FOLD   0.84932180028801905f    // sqrt(1/(2 ln2))
#define TWO_LN2  1.38629436111989062f    // 2 ln2
#define NINV2LN2 (-0.72134752044448170f) // -1/(2 ln2)
#define M2CONST  12582912.0f             // 1.5 * 2^23

// Taylor of 2^(-f), f in [-0.5, 0.5]
#define PC1 (-0.69314718056f)
#define PC2 ( 0.24022650696f)
#define PC3 (-0.05550410866f)
#define PC4 ( 0.00961812911f)

__global__ void prep_kernel(const float* __restrict__ t,
                            const float* __restrict__ sraw,
                            const float* __restrict__ w,
                            int n)
{
    int idx = blockIdx.x * blockDim.x + threadIdx.x;
    if (idx < n) {
        float z  = sraw[idx];
        float sp = log1pf(__expf(z));
        float sc = 0.001f + sp + 1e-8f;
        float iv = 1.0f / sc;
        g_ivc[idx] = C_FOLD * iv;
        g_tin[idx] = -C_FOLD * t[idx] * iv;
        g_w2n[idx] = -TWO_LN2 * w[idx];
    }
}

__global__ __launch_bounds__(256, 3)
void wavelet_kernel(const float* __restrict__ x,
                    float* __restrict__ out,
                    int O)
{
    const int warp = (blockIdx.x * 256 + threadIdx.x) >> 5;
    const int lane = threadIdx.x & 31;
    const int o  = warp >> 6;       // 8 warps (one block) share o
    const int bt = warp & 63;
    const int b0 = bt * RB;

    const ulonglong2* __restrict__ ivp = (const ulonglong2*)(g_ivc + (size_t)o * I_DIM);
    const ulonglong2* __restrict__ tnp = (const ulonglong2*)(g_tin + (size_t)o * I_DIM);
    const ulonglong2* __restrict__ w2p = (const ulonglong2*)(g_w2n + (size_t)o * I_DIM);
    const ulonglong2* __restrict__ xp  = (const ulonglong2*)(x     + (size_t)b0 * I_DIM);

    const u64 KINV = pack2(NINV2LN2, NINV2LN2);
    const u64 M2P  = pack2(M2CONST, M2CONST);
    const u64 M2N  = pack2(-M2CONST, -M2CONST);
    const u64 N1P  = pack2(-1.0f, -1.0f);
    const u64 C1P  = pack2(PC1, PC1);
    const u64 C2P  = pack2(PC2, PC2);
    const u64 C3P  = pack2(PC3, PC3);
    const u64 C4P  = pack2(PC4, PC4);
    const u64 ONEP = pack2(1.0f, 1.0f);

    u64 acc[RB];
#pragma unroll
    for (int b = 0; b < RB; b++) acc[b] = 0ull;

#pragma unroll
    for (int step = 0; step < I_DIM / 128; step++) {
        const int i4 = step * 32 + lane;   // 128-bit index: 128 i per step
        const ulonglong2 iv = ivp[i4];
        const ulonglong2 tn = tnp[i4];
        const ulonglong2 w2 = w2p[i4];
        const u64 wvx = mul2(w2.x, KINV);  // reconstruct w once per step
        const u64 wvy = mul2(w2.y, KINV);

#pragma unroll
        for (int b = 0; b < RB; b++) {
            const ulonglong2 xv = xp[i4 + b * (I_DIM / 4)];
            // poly on pair1 of b=1 and b=5: g = 1/8, evenly interleaved so
            // the FMA-pipe poly work overlaps neighbors' MUFU work.
            const bool poly = (b & 3) == 1;

            // pair 0: MUFU f32 path (always)
            {
                u64 s  = fma2(xv.x, iv.x, tn.x);
                u64 u  = mul2(s, s);
                float e0 = ex2neg(lo32(u));
                float e1 = ex2neg(hi32(u));
                u64 ep = pack2(e0, e1);
                u64 pp = fma2(w2.x, u, wvx);
                acc[b] = fma2(pp, ep, acc[b]);
            }
            // pair 1: poly-exp on FMA pipe for b=1,5; MUFU otherwise
            {
                u64 s  = fma2(xv.y, iv.y, tn.y);
                u64 u  = mul2(s, s);
                u64 pp = fma2(w2.y, u, wvy);
                u64 ep;
                if (poly) {
                    // clamp u to [0,120] for exponent-field safety
                    float ul = fminf(lo32(u), 120.0f);
                    float uh = fminf(hi32(u), 120.0f);
                    u64 uc = pack2(ul, uh);
                    u64 t  = add2(uc, M2P);      // M2 + n (n = round(u))
                    u64 nf = add2(t, M2N);       // n as float (exact, Sterbenz)
                    u64 f  = fma2(nf, N1P, uc);  // f = u - n, in [-0.5, 0.5]
                    u64 P  = fma2(C4P, f, C3P);  // deg-4 Taylor of 2^-f
                    P = fma2(P, f, C2P);
                    P = fma2(P, f, C1P);
                    P = fma2(P, f, ONEP);
                    // e_bits = P_bits - (t_bits << 23); bias term wraps to 0
                    int tb0 = (int)(unsigned)t;
                    int tb1 = (int)(unsigned)(t >> 32);
                    int e0 = __float_as_int(lo32(P)) + tb0 * (-8388608);
                    int e1 = __float_as_int(hi32(P)) + tb1 * (-8388608);
                    ep = pack2(__int_as_float(e0), __int_as_float(e1));
                } else {
                    float e0 = ex2neg(lo32(u));
                    float e1 = ex2neg(hi32(u));
                    ep = pack2(e0, e1);
                }
                acc[b] = fma2(pp, ep, acc[b]);
            }
        }
    }

    // fold packed halves, then warp reduction over i-lanes
#pragma unroll
    for (int b = 0; b < RB; b++) {
        float a = lo32(acc[b]) + hi32(acc[b]);
#pragma unroll
        for (int off = 16; off > 0; off >>= 1)
            a += __shfl_xor_sync(0xFFFFFFFFu, a, off);
        if (lane == 0)
            out[(size_t)(b0 + b) * O + o] = a;
    }
}

extern "C" void kernel_launch(void* const* d_in, const int* in_sizes, int n_in,
                              void* d_out, int out_size)
{
    const float* x    = (const float*)d_in[0];  // (B, I)
    const float* t    = (const float*)d_in[1];  // (O, I)
    const float* sraw = (const float*)d_in[2];  // (O, I)
    const float* w    = (const float*)d_in[3];  // (O, I)
    float* out = (float*)d_out;                 // (B, O)

    const int OI = in_sizes[1];          // O * I
    const int BI = in_sizes[0];          // B * I
    const int O  = OI / I_DIM;           // 1024
    const int B  = BI / I_DIM;           // 512
    const int nbt = B / RB;              // 64

    prep_kernel<<<(OI + 255) / 256, 256>>>(t, sraw, w, OI);

    const int total_warps = O * nbt;
    wavelet_kernel<<<total_warps / 8, 256>>>(x, out, O);
}

// round 15
// speedup vs baseline: 1.2553x; 1.0887x over previous
#include <cuda_runtime.h>
#include <cuda_bf16.h>

// WaveletLinear: y[b,o] = sum_i w[o,i] * (1 - s^2) * exp(-0.5 s^2),
//   s = (x[b,i] - t[o,i]) / (A_MIN + softplus(scale_raw[o,i]) + EPS)
// B=512, O=1024, I=512.
//
// FINAL (validated across 14 rounds): this configuration runs at ~100% of
// the f32-MUFU floor (2x EX2 per packed pair, rt8/SMSP -> 113K cyc), which
// is the true binding resource. All offload variants (f16x2 ex2, FMA-pipe
// polynomial exp2, hybrid mixes, occupancy/layout changes) measured slower:
// cvt ops run ~rt4 on the XU pipe and poly bursts de-pack MUFU issue density.
//
// Math:  c^2 = 1/(2 ln2),  u = (c*s)^2  (>=0)
//   exp(-0.5 s^2) = ex2(-u)          (neg folds into the MUFU operand)
//   w*(1 - s^2)   = fma(w2n, u, w),  w2n = -2ln2*w,  w = w2n * (-1/(2ln2))
// Packed f32x2 FMAs keep the fma pipe (11 cyc/pair w/ RF banking) under the
// MUFU floor (16 cyc/pair). 3 precomputed streams; w reconstructed per step.

#define I_DIM 512
#define RB 8   // batch rows per warp

typedef unsigned long long u64;

__device__ float g_ivc[1024 * 512];
__device__ float g_tin[1024 * 512];
__device__ float g_w2n[1024 * 512];

__device__ __forceinline__ u64 fma2(u64 a, u64 b, u64 c) {
    u64 d; asm("fma.rn.f32x2 %0, %1, %2, %3;" : "=l"(d) : "l"(a), "l"(b), "l"(c)); return d;
}
__device__ __forceinline__ u64 mul2(u64 a, u64 b) {
    u64 d; asm("mul.rn.f32x2 %0, %1, %2;" : "=l"(d) : "l"(a), "l"(b)); return d;
}
__device__ __forceinline__ float ex2neg(float a) {
    float r;
    asm("{ .reg .f32 t; neg.f32 t, %1; ex2.approx.ftz.f32 %0, t; }" : "=f"(r) : "f"(a));
    return r;
}
__device__ __forceinline__ u64 pack2(float lo, float hi) {
    u64 d; asm("mov.b64 %0, {%1, %2};" : "=l"(d) : "f"(lo), "f"(hi)); return d;
}
__device__ __forceinline__ float lo32(u64 v) { return __uint_as_float((unsigned)v); }
__device__ __forceinline__ float hi32(u64 v) { return __uint_as_float((unsigned)(v >> 32)); }

#define C_FOLD   0.84932180028801905f    // sqrt(1/(2 ln2))
#define TWO_LN2  1.38629436111989062f    // 2 ln2
#define NINV2LN2 (-0.72134752044448170f) // -1/(2 ln2)

__global__ void prep_kernel(const float* __restrict__ t,
                            const float* __restrict__ sraw,
                            const float* __restrict__ w,
                            int n)
{
    int idx = blockIdx.x * blockDim.x + threadIdx.x;
    if (idx < n) {
        float z  = sraw[idx];
        float sp = log1pf(__expf(z));
        float sc = 0.001f + sp + 1e-8f;
        float iv = 1.0f / sc;
        g_ivc[idx] = C_FOLD * iv;
        g_tin[idx] = -C_FOLD * t[idx] * iv;
        g_w2n[idx] = -TWO_LN2 * w[idx];
    }
}

__global__ __launch_bounds__(256, 3)
void wavelet_kernel(const float* __restrict__ x,
                    float* __restrict__ out,
                    int O)
{
    const int warp = (blockIdx.x * 256 + threadIdx.x) >> 5;
    const int lane = threadIdx.x & 31;
    const int o  = warp >> 6;       // 8 warps (one block) share o
    const int bt = warp & 63;
    const int b0 = bt * RB;

    const ulonglong2* __restrict__ ivp = (const ulonglong2*)(g_ivc + (size_t)o * I_DIM);
    const ulonglong2* __restrict__ tnp = (const ulonglong2*)(g_tin + (size_t)o * I_DIM);
    const ulonglong2* __restrict__ w2p = (const ulonglong2*)(g_w2n + (size_t)o * I_DIM);
    const ulonglong2* __restrict__ xp  = (const ulonglong2*)(x     + (size_t)b0 * I_DIM);

    const u64 KINV = pack2(NINV2LN2, NINV2LN2);

    u64 acc[RB];
#pragma unroll
    for (int b = 0; b < RB; b++) acc[b] = 0ull;

#pragma unroll
    for (int step = 0; step < I_DIM / 128; step++) {
        const int i4 = step * 32 + lane;   // 128-bit index: 128 i per step
        const ulonglong2 iv = ivp[i4];
        const ulonglong2 tn = tnp[i4];
        const ulonglong2 w2 = w2p[i4];
        // reconstruct w from w2n once per step (shared by all RB rows)
        const u64 wvx = mul2(w2.x, KINV);
        const u64 wvy = mul2(w2.y, KINV);

#pragma unroll
        for (int b = 0; b < RB; b++) {
            const ulonglong2 xv = xp[i4 + b * (I_DIM / 4)];

            // pair 0
            {
                u64 s  = fma2(xv.x, iv.x, tn.x);
                u64 u  = mul2(s, s);
                float e0 = ex2neg(lo32(u));
                float e1 = ex2neg(hi32(u));
                u64 ep = pack2(e0, e1);
                u64 pp = fma2(w2.x, u, wvx);
                acc[b] = fma2(pp, ep, acc[b]);
            }
            // pair 1
            {
                u64 s  = fma2(xv.y, iv.y, tn.y);
                u64 u  = mul2(s, s);
                float e0 = ex2neg(lo32(u));
                float e1 = ex2neg(hi32(u));
                u64 ep = pack2(e0, e1);
                u64 pp = fma2(w2.y, u, wvy);
                acc[b] = fma2(pp, ep, acc[b]);
            }
        }
    }

    // fold packed halves, then warp reduction over i-lanes
#pragma unroll
    for (int b = 0; b < RB; b++) {
        float a = lo32(acc[b]) + hi32(acc[b]);
#pragma unroll
        for (int off = 16; off > 0; off >>= 1)
            a += __shfl_xor_sync(0xFFFFFFFFu, a, off);
        if (lane == 0)
            out[(size_t)(b0 + b) * O + o] = a;
    }
}

extern "C" void kernel_launch(void* const* d_in, const int* in_sizes, int n_in,
                              void* d_out, int out_size)
{
    const float* x    = (const float*)d_in[0];  // (B, I)
    const float* t    = (const float*)d_in[1];  // (O, I)
    const float* sraw = (const float*)d_in[2];  // (O, I)
    const float* w    = (const float*)d_in[3];  // (O, I)
    float* out = (float*)d_out;                 // (B, O)

    const int OI = in_sizes[1];          // O * I
    const int BI = in_sizes[0];          // B * I
    const int O  = OI / I_DIM;           // 1024
    const int B  = BI / I_DIM;           // 512
    const int nbt = B / RB;              // 64

    prep_kernel<<<(OI + 255) / 256, 256>>>(t, sraw, w, OI);

    const int total_warps = O * nbt;
    wavelet_kernel<<<total_warps / 8, 256>>>(x, out, O);
}

// round 16
// speedup vs baseline: 1.2559x; 1.0004x over previous
#include <cuda_runtime.h>
#include <cuda_bf16.h>

// WaveletLinear: y[b,o] = sum_i w[o,i] * (1 - s^2) * exp(-0.5 s^2),
//   s = (x[b,i] - t[o,i]) / (A_MIN + softplus(scale_raw[o,i]) + EPS)
// B=512, O=1024, I=512.
//
// FINAL — at the hardware roofline (validated over 15 rounds):
// Binding resource: 1 f32 EX2 per element = 8.4M warp-EX2 / (592 SMSP / rt8)
// = 113K cycles = 72.3us @ ~1.57GHz NAT. This kernel measures 72.2us = ~100%
// of the MUFU floor. Closed-out alternatives (all measured slower):
//  - f16x2 ex2 (4 variants): cvt glue >= MUFU saved, chain de-densification
//  - FMA-pipe polynomial exp2 (3 variants): realized 120K+ cyc vs 99K theory
//  - occupancy 35->49%: no effect (MUFU lat 16 saturates with ~2 warps)
//  - locality layouts: memory never binding (DRAM 1.2%)
// No mathematical reduction of the exp count exists (argument is per-(b,o,i)).
//
// Math:  c^2 = 1/(2 ln2),  u = (c*s)^2  (>=0)
//   exp(-0.5 s^2) = ex2(-u)          (neg folds into the MUFU operand)
//   w*(1 - s^2)   = fma(w2n, u, w),  w2n = -2ln2*w,  w = w2n * (-1/(2ln2))
// Packed f32x2 FMAs keep the fma pipe (11 bank-cyc/pair) under the MUFU
// floor (16 cyc/pair). 3 precomputed streams; w reconstructed per step.

#define I_DIM 512
#define RB 8   // batch rows per warp

typedef unsigned long long u64;

__device__ float g_ivc[1024 * 512];
__device__ float g_tin[1024 * 512];
__device__ float g_w2n[1024 * 512];

__device__ __forceinline__ u64 fma2(u64 a, u64 b, u64 c) {
    u64 d; asm("fma.rn.f32x2 %0, %1, %2, %3;" : "=l"(d) : "l"(a), "l"(b), "l"(c)); return d;
}
__device__ __forceinline__ u64 mul2(u64 a, u64 b) {
    u64 d; asm("mul.rn.f32x2 %0, %1, %2;" : "=l"(d) : "l"(a), "l"(b)); return d;
}
__device__ __forceinline__ float ex2neg(float a) {
    float r;
    asm("{ .reg .f32 t; neg.f32 t, %1; ex2.approx.ftz.f32 %0, t; }" : "=f"(r) : "f"(a));
    return r;
}
__device__ __forceinline__ u64 pack2(float lo, float hi) {
    u64 d; asm("mov.b64 %0, {%1, %2};" : "=l"(d) : "f"(lo), "f"(hi)); return d;
}
__device__ __forceinline__ float lo32(u64 v) { return __uint_as_float((unsigned)v); }
__device__ __forceinline__ float hi32(u64 v) { return __uint_as_float((unsigned)(v >> 32)); }

#define C_FOLD   0.84932180028801905f    // sqrt(1/(2 ln2))
#define TWO_LN2  1.38629436111989062f    // 2 ln2
#define NINV2LN2 (-0.72134752044448170f) // -1/(2 ln2)

__global__ void prep_kernel(const float* __restrict__ t,
                            const float* __restrict__ sraw,
                            const float* __restrict__ w,
                            int n)
{
    int idx = blockIdx.x * blockDim.x + threadIdx.x;
    if (idx < n) {
        float z  = sraw[idx];
        float sp = log1pf(__expf(z));
        float sc = 0.001f + sp + 1e-8f;
        float iv = 1.0f / sc;
        g_ivc[idx] = C_FOLD * iv;
        g_tin[idx] = -C_FOLD * t[idx] * iv;
        g_w2n[idx] = -TWO_LN2 * w[idx];
    }
}

__global__ __launch_bounds__(256, 3)
void wavelet_kernel(const float* __restrict__ x,
                    float* __restrict__ out,
                    int O)
{
    const int warp = (blockIdx.x * 256 + threadIdx.x) >> 5;
    const int lane = threadIdx.x & 31;
    const int o  = warp >> 6;       // 8 warps (one block) share o
    const int bt = warp & 63;
    const int b0 = bt * RB;

    const ulonglong2* __restrict__ ivp = (const ulonglong2*)(g_ivc + (size_t)o * I_DIM);
    const ulonglong2* __restrict__ tnp = (const ulonglong2*)(g_tin + (size_t)o * I_DIM);
    const ulonglong2* __restrict__ w2p = (const ulonglong2*)(g_w2n + (size_t)o * I_DIM);
    const ulonglong2* __restrict__ xp  = (const ulonglong2*)(x     + (size_t)b0 * I_DIM);

    const u64 KINV = pack2(NINV2LN2, NINV2LN2);

    u64 acc[RB];
#pragma unroll
    for (int b = 0; b < RB; b++) acc[b] = 0ull;

#pragma unroll
    for (int step = 0; step < I_DIM / 128; step++) {
        const int i4 = step * 32 + lane;   // 128-bit index: 128 i per step
        const ulonglong2 iv = ivp[i4];
        const ulonglong2 tn = tnp[i4];
        const ulonglong2 w2 = w2p[i4];
        // reconstruct w from w2n once per step (shared by all RB rows)
        const u64 wvx = mul2(w2.x, KINV);
        const u64 wvy = mul2(w2.y, KINV);

#pragma unroll
        for (int b = 0; b < RB; b++) {
            const ulonglong2 xv = xp[i4 + b * (I_DIM / 4)];

            // pair 0
            {
                u64 s  = fma2(xv.x, iv.x, tn.x);
                u64 u  = mul2(s, s);
                float e0 = ex2neg(lo32(u));
                float e1 = ex2neg(hi32(u));
                u64 ep = pack2(e0, e1);
                u64 pp = fma2(w2.x, u, wvx);
                acc[b] = fma2(pp, ep, acc[b]);
            }
            // pair 1
            {
                u64 s  = fma2(xv.y, iv.y, tn.y);
                u64 u  = mul2(s, s);
                float e0 = ex2neg(lo32(u));
                float e1 = ex2neg(hi32(u));
                u64 ep = pack2(e0, e1);
                u64 pp = fma2(w2.y, u, wvy);
                acc[b] = fma2(pp, ep, acc[b]);
            }
        }
    }

    // fold packed halves, then warp reduction over i-lanes
#pragma unroll
    for (int b = 0; b < RB; b++) {
        float a = lo32(acc[b]) + hi32(acc[b]);
#pragma unroll
        for (int off = 16; off > 0; off >>= 1)
            a += __shfl_xor_sync(0xFFFFFFFFu, a, off);
        if (lane == 0)
            out[(size_t)(b0 + b) * O + o] = a;
    }
}

extern "C" void kernel_launch(void* const* d_in, const int* in_sizes, int n_in,
                              void* d_out, int out_size)
{
    const float* x    = (const float*)d_in[0];  // (B, I)
    const float* t    = (const float*)d_in[1];  // (O, I)
    const float* sraw = (const float*)d_in[2];  // (O, I)
    const float* w    = (const float*)d_in[3];  // (O, I)
    float* out = (float*)d_out;                 // (B, O)

    const int OI = in_sizes[1];          // O * I
    const int BI = in_sizes[0];          // B * I
    const int O  = OI / I_DIM;           // 1024
    const int B  = BI / I_DIM;           // 512
    const int nbt = B / RB;              // 64

    prep_kernel<<<(OI + 255) / 256, 256>>>(t, sraw, w, OI);

    const int total_warps = O * nbt;
    wavelet_kernel<<<total_warps / 8, 256>>>(x, out, O);
}